// round 12
// baseline (speedup 1.0000x reference)
#include <cuda_runtime.h>
#include <cuda_fp16.h>
#include <math.h>
#include <stdint.h>

// Problem constants
#define B_  64
#define T_  1024
#define C_  256
#define BR  64               // query rows per CTA (= key tile)
#define NTILE (T_ / BR)      // 16
#define OSS 260              // final O staging stride (floats)

// SMEM byte offsets (per CTA ~100.5 KB -> 2 CTAs/SM)
#define OF_Q   0             // 64 rows x 528B
#define OF_X0  33792         // 64 rows x 528B (double-buffered K=V tile)
#define OF_X1  67584
#define OF_MU  101376        // mu[64]
#define OF_RS  101632        // rstd[64]
#define OF_CS  101888        // colsum/1024 [256]  (never aliased by Os/X)
#define SMEM_TOTAL 102912

// Device scratch
__device__ __half g_xh[B_ * T_ * C_];
__device__ float  g_cs16[B_ * 16 * C_];   // per-64-row colsum partials
__device__ float  g_part[B_ * NTILE * C_];

// ---------------------------------------------------------------------------
static __device__ __forceinline__ uint32_t smem_u32(const void* p) {
    return (uint32_t)__cvta_generic_to_shared(p);
}
static __device__ __forceinline__ void cp16(uint32_t dst, const void* src) {
    asm volatile("cp.async.cg.shared.global [%0], [%1], 16;" :: "r"(dst), "l"(src));
}
static __device__ __forceinline__ void ldsm4(
    uint32_t& r0, uint32_t& r1, uint32_t& r2, uint32_t& r3, uint32_t a)
{
    asm volatile("ldmatrix.sync.aligned.m8n8.x4.shared.b16 {%0,%1,%2,%3}, [%4];"
                 : "=r"(r0), "=r"(r1), "=r"(r2), "=r"(r3) : "r"(a));
}
static __device__ __forceinline__ void ldsm4t(
    uint32_t& r0, uint32_t& r1, uint32_t& r2, uint32_t& r3, uint32_t a)
{
    asm volatile("ldmatrix.sync.aligned.m8n8.x4.trans.shared.b16 {%0,%1,%2,%3}, [%4];"
                 : "=r"(r0), "=r"(r1), "=r"(r2), "=r"(r3) : "r"(a));
}
static __device__ __forceinline__ void mma_f16(
    float* d, uint32_t a0, uint32_t a1, uint32_t a2, uint32_t a3,
    uint32_t b0, uint32_t b1)
{
    asm volatile(
        "mma.sync.aligned.m16n8k16.row.col.f32.f16.f16.f32 "
        "{%0,%1,%2,%3},{%4,%5,%6,%7},{%8,%9},{%0,%1,%2,%3};"
        : "+f"(d[0]), "+f"(d[1]), "+f"(d[2]), "+f"(d[3])
        : "r"(a0), "r"(a1), "r"(a2), "r"(a3), "r"(b0), "r"(b1));
}
static __device__ __forceinline__ uint32_t packh2(float x, float y) {
    __half2 h = __floats2half2_rn(x, y);
    return *(uint32_t*)&h;
}

// ---------------------------------------------------------------------------
// Kernel 1: fp16 copy of x + exact fp32 colsum partials
// ---------------------------------------------------------------------------
__global__ void prep_kernel(const float* __restrict__ x) {
    const int b = blockIdx.x, ch = blockIdx.y, c = threadIdx.x;
    const size_t base = ((size_t)b * T_ + (size_t)ch * 64) * C_ + c;
    const float* xp = x + base;
    __half* op = g_xh + base;
    float s = 0.f;
#pragma unroll 8
    for (int t = 0; t < 64; t++) {
        float v = xp[(size_t)t * C_];
        s += v;
        op[(size_t)t * C_] = __float2half_rn(v);
    }
    g_cs16[(b * 16 + ch) * C_ + c] = s;
}

// ---------------------------------------------------------------------------
// Kernel 2: flash attention, fp16 mma, register-resident P + in-register
// online softmax. Heavy-first launch; diag-tile MMA skip; per-CTA colsum
// reduction folded into the epilogue. 128 thr, 2 CTAs/SM.
// ---------------------------------------------------------------------------
__global__ void __launch_bounds__(128, 2)
attn_kernel(const int* __restrict__ km, const float* __restrict__ gamma,
            const float* __restrict__ beta)
{
    extern __shared__ char smc[];
    float* smf = (float*)smc;
    const uint32_t sb = smem_u32(smc);

    const int qt   = 15 - blockIdx.y;        // ALL heavy tiles launch first
    const int b    = blockIdx.x;
    const int tid  = threadIdx.x;
    const int lane = tid & 31;
    const int w    = tid >> 5;
    const int jj   = lane & 3;
    const int g8   = lane >> 2;
    const int l15  = lane & 15;
    const int lh   = lane >> 4;
    const int q0   = qt * BR;
    const int row0 = w * 16 + g8;            // local q row (second: +8)
    const int grow0 = q0 + row0, grow1 = grow0 + 8;
    const __half* xb = g_xh + (size_t)b * T_ * C_;

    const uint32_t aQ = sb + OF_Q + (uint32_t)(w * 16 + l15) * 528 + lh * 16;

    // Prefetch Q + X tile 0 (one group)
#pragma unroll
    for (int it = 0; it < 16; it++) {
        int idx = tid + it * 128;
        int r = idx >> 5, g = idx & 31;
        cp16(sb + OF_Q + r * 528 + g * 16, xb + (size_t)(q0 + r) * C_ + g * 8);
    }
#pragma unroll
    for (int it = 0; it < 16; it++) {
        int idx = tid + it * 128;
        int r = idx >> 5, g = idx & 31;
        cp16(sb + OF_X0 + r * 528 + g * 16, xb + (size_t)r * C_ + g * 8);
    }
    asm volatile("cp.async.commit_group;");

    float Oacc[32][4];
#pragma unroll
    for (int i = 0; i < 32; i++)
#pragma unroll
        for (int e = 0; e < 4; e++) Oacc[i][e] = 0.f;
    float m0 = -INFINITY, m1 = -INFINITY, l0 = 0.f, l1 = 0.f;

    for (int st = 0; st <= qt; st++) {
        const uint32_t Xoff = (st & 1) ? OF_X1 : OF_X0;
        const int s0 = st * BR;
        const bool diag = (st == qt);

        asm volatile("cp.async.wait_group 0;");
        __syncthreads();                      // X[st] visible; X[(st+1)&1] free

        if (st < qt) {                        // prefetch next tile
            const uint32_t Xn = ((st + 1) & 1) ? OF_X1 : OF_X0;
            const __half* src = xb + (size_t)(st + 1) * BR * C_;
#pragma unroll
            for (int it = 0; it < 16; it++) {
                int idx = tid + it * 128;
                int r = idx >> 5, g = idx & 31;
                cp16(sb + Xn + r * 528 + g * 16, src + (size_t)r * C_ + g * 8);
            }
            asm volatile("cp.async.commit_group;");
        }

        // key-padding mask pairs for my 16 columns
        int2 kmv[8];
#pragma unroll
        for (int nt = 0; nt < 8; nt++)
            kmv[nt] = *(const int2*)(km + b * T_ + s0 + nt * 8 + 2 * jj);

        // ---- Stage A: S = Q K^T, warp tile 16x64 ----
        uint32_t aK[4];
#pragma unroll
        for (int nb = 0; nb < 4; nb++)
            aK[nb] = sb + Xoff + (uint32_t)(nb * 16 + (lane & 7) + lh * 8) * 528
                     + ((lane >> 3) & 1) * 16;
        const int nbmax = diag ? (w + 1) : 4;   // warp-uniform

        float sacc[8][4];
#pragma unroll
        for (int nt = 0; nt < 8; nt++)
#pragma unroll
            for (int e = 0; e < 4; e++) sacc[nt][e] = 0.f;

#pragma unroll
        for (int k = 0; k < 16; k++) {
            uint32_t a0, a1, a2, a3;
            ldsm4(a0, a1, a2, a3, aQ + k * 32);
#pragma unroll
            for (int nb = 0; nb < 4; nb++) {
                if (nb < nbmax) {
                    uint32_t b0, b1, b2, b3;
                    ldsm4(b0, b1, b2, b3, aK[nb] + k * 32);
                    mma_f16(sacc[2 * nb],     a0, a1, a2, a3, b0, b1);
                    mma_f16(sacc[2 * nb + 1], a0, a1, a2, a3, b2, b3);
                }
            }
        }

        // ---- Mask + in-register online softmax (quad shuffles only) ----
#pragma unroll
        for (int nt = 0; nt < 8; nt++) {
#pragma unroll
            for (int e = 0; e < 2; e++) {
                int key = s0 + nt * 8 + 2 * jj + e;
                int ok = e ? kmv[nt].y : kmv[nt].x;
                sacc[nt][e]     = ((key <= grow0) && ok) ? sacc[nt][e] * 0.0625f     : -INFINITY;
                sacc[nt][2 + e] = ((key <= grow1) && ok) ? sacc[nt][2 + e] * 0.0625f : -INFINITY;
            }
        }
        float mt0 = -INFINITY, mt1 = -INFINITY;
#pragma unroll
        for (int nt = 0; nt < 8; nt++) {
            mt0 = fmaxf(mt0, fmaxf(sacc[nt][0], sacc[nt][1]));
            mt1 = fmaxf(mt1, fmaxf(sacc[nt][2], sacc[nt][3]));
        }
        mt0 = fmaxf(mt0, __shfl_xor_sync(0xffffffffu, mt0, 1));
        mt0 = fmaxf(mt0, __shfl_xor_sync(0xffffffffu, mt0, 2));
        mt1 = fmaxf(mt1, __shfl_xor_sync(0xffffffffu, mt1, 1));
        mt1 = fmaxf(mt1, __shfl_xor_sync(0xffffffffu, mt1, 2));
        const float mn0 = fmaxf(m0, mt0), mn1 = fmaxf(m1, mt1);
        const float al0 = (m0 == -INFINITY) ? 0.f : __expf(m0 - mn0);
        const float al1 = (m1 == -INFINITY) ? 0.f : __expf(m1 - mn1);

        float p0[8][2], p1[8][2], sum0 = 0.f, sum1 = 0.f;
#pragma unroll
        for (int nt = 0; nt < 8; nt++) {
#pragma unroll
            for (int e = 0; e < 2; e++) {
                float a = sacc[nt][e],     pa = (a == -INFINITY) ? 0.f : __expf(a - mn0);
                float c = sacc[nt][2 + e], pc = (c == -INFINITY) ? 0.f : __expf(c - mn1);
                p0[nt][e] = pa; sum0 += pa;
                p1[nt][e] = pc; sum1 += pc;
            }
        }
        sum0 += __shfl_xor_sync(0xffffffffu, sum0, 1);
        sum0 += __shfl_xor_sync(0xffffffffu, sum0, 2);
        sum1 += __shfl_xor_sync(0xffffffffu, sum1, 1);
        sum1 += __shfl_xor_sync(0xffffffffu, sum1, 2);
        l0 = l0 * al0 + sum0;  m0 = mn0;
        l1 = l1 * al1 + sum1;  m1 = mn1;

        // rescale O accumulators
#pragma unroll
        for (int i = 0; i < 32; i++) {
            Oacc[i][0] *= al0; Oacc[i][1] *= al0;
            Oacc[i][2] *= al1; Oacc[i][3] *= al1;
        }

        // pack P into A-fragments (C-frag layout == A-frag layout)
        uint32_t pA[4][4];
#pragma unroll
        for (int kb = 0; kb < 4; kb++) {
            pA[kb][0] = packh2(p0[2 * kb][0],     p0[2 * kb][1]);
            pA[kb][1] = packh2(p1[2 * kb][0],     p1[2 * kb][1]);
            pA[kb][2] = packh2(p0[2 * kb + 1][0], p0[2 * kb + 1][1]);
            pA[kb][3] = packh2(p1[2 * kb + 1][0], p1[2 * kb + 1][1]);
        }

        // ---- Stage B: O += P @ X, warp tile 16x256 ----
        const uint32_t aXb = sb + Xoff + (uint32_t)l15 * 528 + lh * 16;
        const int ksmax = diag ? (w + 1) : 4;   // warp-uniform
#pragma unroll
        for (int ks = 0; ks < 4; ks++) {
            if (ks < ksmax) {
#pragma unroll
                for (int n16 = 0; n16 < 16; n16++) {
                    uint32_t x0, x1, x2, x3;
                    ldsm4t(x0, x1, x2, x3, aXb + ks * 16 * 528 + n16 * 32);
                    mma_f16(Oacc[2 * n16],     pA[ks][0], pA[ks][1], pA[ks][2], pA[ks][3], x0, x1);
                    mma_f16(Oacc[2 * n16 + 1], pA[ks][0], pA[ks][1], pA[ks][2], pA[ks][3], x2, x3);
                }
            }
        }
    }

    // ---- per-CTA colsum reduction (pre-scaled) into never-aliased smem ----
    // Written after this thread's loop; published by the sync below.
    {
        float s0 = 0.f, s1 = 0.f;
#pragma unroll
        for (int i = 0; i < 16; i++) {
            s0 += g_cs16[(b * 16 + i) * C_ + tid];
            s1 += g_cs16[(b * 16 + i) * C_ + tid + 128];
        }
        smf[OF_CS / 4 + tid]       = s0 * (1.f / 1024.f);
        smf[OF_CS / 4 + tid + 128] = s1 * (1.f / 1024.f);
    }

    // ---- Epilogue: normalize / degenerate fixup -> Os staging ----
    __syncthreads();                           // all compute done; csum visible
    float* Os = smf;
    const float* csum = smf + OF_CS / 4;
    {
        const bool d0 = (l0 == 0.f), d1 = (l1 == 0.f);
        const float inv0 = d0 ? 0.f : (1.f / l0);
        const float inv1 = d1 ? 0.f : (1.f / l1);
#pragma unroll
        for (int nt2 = 0; nt2 < 32; nt2++)
#pragma unroll
            for (int e = 0; e < 2; e++) {
                const int c = nt2 * 8 + 2 * jj + e;
                const float cm = csum[c];
                Os[row0 * OSS + c]       = d0 ? cm : Oacc[nt2][e] * inv0;
                Os[(row0 + 8) * OSS + c] = d1 ? cm : Oacc[nt2][2 + e] * inv1;
            }
    }
    __syncthreads();

    // ---- LayerNorm stats (2 threads per row) ----
    {
        const int r = tid >> 1, hf = tid & 1;
        const float* row = Os + r * OSS + hf * 128;
        float s1 = 0.f;
#pragma unroll 8
        for (int c = 0; c < 128; c++) s1 += row[c];
        s1 += __shfl_xor_sync(0xffffffffu, s1, 1);
        const float mu = s1 * (1.f / 256.f);
        float s2 = 0.f;
#pragma unroll 8
        for (int c = 0; c < 128; c++) { float d = row[c] - mu; s2 += d * d; }
        s2 += __shfl_xor_sync(0xffffffffu, s2, 1);
        const float rstd = rsqrtf(s2 * (1.f / 256.f) + 1e-9f);
        if (hf == 0) { smf[OF_MU / 4 + r] = mu; smf[OF_RS / 4 + r] = rstd; }
    }
    __syncthreads();

    // ---- Column partials (each thread: cols tid, tid+128) ----
    {
        float acc0 = 0.f, acc1 = 0.f;
#pragma unroll 4
        for (int r = 0; r < BR; r++) {
            const float muv = smf[OF_MU / 4 + r], rsv = smf[OF_RS / 4 + r];
            acc0 += (Os[r * OSS + tid]       - muv) * rsv;
            acc1 += (Os[r * OSS + tid + 128] - muv) * rsv;
        }
        float* gp = g_part + (size_t)(b * NTILE + qt) * C_;
        gp[tid]       = gamma[tid]       * acc0 + 64.f * beta[tid];
        gp[tid + 128] = gamma[tid + 128] * acc1 + 64.f * beta[tid + 128];
    }
}

// ---------------------------------------------------------------------------
// Kernel 3: reduce q-tile partials -> mean over T
// ---------------------------------------------------------------------------
__global__ void finalize_kernel(float* __restrict__ out) {
    const int b = blockIdx.x, c = threadIdx.x;
    float s = 0.f;
#pragma unroll
    for (int qtl = 0; qtl < NTILE; qtl++) s += g_part[(b * NTILE + qtl) * C_ + c];
    out[b * C_ + c] = s * (1.f / 1024.f);
}

// ---------------------------------------------------------------------------
extern "C" void kernel_launch(void* const* d_in, const int* in_sizes, int n_in,
                              void* d_out, int out_size)
{
    const float* x     = (const float*)d_in[0];
    const int*   km    = (const int*)  d_in[1];
    const float* gamma = (const float*)d_in[2];
    const float* beta  = (const float*)d_in[3];
    float*       out   = (float*)d_out;

    cudaFuncSetAttribute(attn_kernel,
                         cudaFuncAttributeMaxDynamicSharedMemorySize, SMEM_TOTAL);

    prep_kernel<<<dim3(B_, 16), 256>>>(x);
    attn_kernel<<<dim3(B_, NTILE), 128, SMEM_TOTAL>>>(km, gamma, beta);
    finalize_kernel<<<B_, 256>>>(out);
}

// round 13
// speedup vs baseline: 1.2357x; 1.2357x over previous
#include <cuda_runtime.h>
#include <cuda_fp16.h>
#include <math.h>
#include <stdint.h>

// Problem constants
#define B_  64
#define T_  1024
#define C_  256
#define BR  64               // query rows per CTA (= key tile)
#define NTILE (T_ / BR)      // 16
#define OSS 260              // final O staging stride (floats)

// SMEM byte offsets (per CTA ~100.5 KB -> 2 CTAs/SM)
#define OF_Q   0             // 64 rows x 528B
#define OF_X0  33792         // 64 rows x 528B (double-buffered compacted K=V)
#define OF_X1  67584
#define OF_MU  101376        // mu[64]
#define OF_RS  101632        // rstd[64]
#define OF_CS  101888        // colsum/1024 [256] (never aliased)
#define SMEM_TOTAL 102912

#define PAD_IDX 0x3FFFFFFF

// Device scratch
__device__ __half g_xh[B_ * T_ * C_];     // fp16 copy of x (queries + gather src)
__device__ __half g_xc[B_ * T_ * C_];     // compacted valid keys (fp16), zero-padded
__device__ int    g_kidx[B_ * T_];        // orig index per compacted key (pad: PAD_IDX)
__device__ int    g_cnt[B_ * NTILE];      // # valid keys with idx < (qt+1)*64
__device__ float  g_cs16[B_ * 16 * C_];   // colsum partials
__device__ float  g_part[B_ * NTILE * C_];

// ---------------------------------------------------------------------------
static __device__ __forceinline__ uint32_t smem_u32(const void* p) {
    return (uint32_t)__cvta_generic_to_shared(p);
}
static __device__ __forceinline__ void cp16(uint32_t dst, const void* src) {
    asm volatile("cp.async.cg.shared.global [%0], [%1], 16;" :: "r"(dst), "l"(src));
}
static __device__ __forceinline__ void ldsm4(
    uint32_t& r0, uint32_t& r1, uint32_t& r2, uint32_t& r3, uint32_t a)
{
    asm volatile("ldmatrix.sync.aligned.m8n8.x4.shared.b16 {%0,%1,%2,%3}, [%4];"
                 : "=r"(r0), "=r"(r1), "=r"(r2), "=r"(r3) : "r"(a));
}
static __device__ __forceinline__ void ldsm4t(
    uint32_t& r0, uint32_t& r1, uint32_t& r2, uint32_t& r3, uint32_t a)
{
    asm volatile("ldmatrix.sync.aligned.m8n8.x4.trans.shared.b16 {%0,%1,%2,%3}, [%4];"
                 : "=r"(r0), "=r"(r1), "=r"(r2), "=r"(r3) : "r"(a));
}
static __device__ __forceinline__ void mma_f16(
    float* d, uint32_t a0, uint32_t a1, uint32_t a2, uint32_t a3,
    uint32_t b0, uint32_t b1)
{
    asm volatile(
        "mma.sync.aligned.m16n8k16.row.col.f32.f16.f16.f32 "
        "{%0,%1,%2,%3},{%4,%5,%6,%7},{%8,%9},{%0,%1,%2,%3};"
        : "+f"(d[0]), "+f"(d[1]), "+f"(d[2]), "+f"(d[3])
        : "r"(a0), "r"(a1), "r"(a2), "r"(a3), "r"(b0), "r"(b1));
}
static __device__ __forceinline__ uint32_t packh2(float x, float y) {
    __half2 h = __floats2half2_rn(x, y);
    return *(uint32_t*)&h;
}

// ---------------------------------------------------------------------------
// Kernel 1: fp16 copy of x + exact fp32 colsum partials
// ---------------------------------------------------------------------------
__global__ void prep_kernel(const float* __restrict__ x) {
    const int b = blockIdx.x, ch = blockIdx.y, c = threadIdx.x;
    const size_t base = ((size_t)b * T_ + (size_t)ch * 64) * C_ + c;
    const float* xp = x + base;
    __half* op = g_xh + base;
    float s = 0.f;
#pragma unroll 8
    for (int t = 0; t < 64; t++) {
        float v = xp[(size_t)t * C_];
        s += v;
        op[(size_t)t * C_] = __float2half_rn(v);
    }
    g_cs16[(b * 16 + ch) * C_ + c] = s;
}

// ---------------------------------------------------------------------------
// Kernel 1b: per-batch key compaction. One CTA (256 thr) per batch.
// Prefix-sum km -> stable list of valid keys; gather fp16 rows; zero pads.
// ---------------------------------------------------------------------------
__global__ void compact_kernel(const int* __restrict__ km) {
    __shared__ int list[T_];
    __shared__ int wsum[8];
    __shared__ int incl[256];
    __shared__ int total_s;

    const int b = blockIdx.x, tid = threadIdx.x;
    const int lane = tid & 31, wp = tid >> 5;

    int4 f = ((const int4*)(km + b * T_))[tid];   // flags for keys 4tid..4tid+3
    int c0 = (f.x != 0), c1 = (f.y != 0), c2 = (f.z != 0), c3 = (f.w != 0);
    int cnt4 = c0 + c1 + c2 + c3;

    // warp inclusive scan of cnt4
    int v = cnt4;
#pragma unroll
    for (int off = 1; off < 32; off <<= 1) {
        int n = __shfl_up_sync(0xffffffffu, v, off);
        if (lane >= off) v += n;
    }
    if (lane == 31) wsum[wp] = v;
    __syncthreads();
    if (tid == 0) {
        int running = 0;
#pragma unroll
        for (int i = 0; i < 8; i++) { int t = wsum[i]; wsum[i] = running; running += t; }
        total_s = running;
    }
    __syncthreads();
    const int excl = v - cnt4 + wsum[wp];
    incl[tid] = excl + cnt4;

    int base = excl;
    const int t0 = tid * 4;
    if (c0) list[base++] = t0;
    if (c1) list[base++] = t0 + 1;
    if (c2) list[base++] = t0 + 2;
    if (c3) list[base++] = t0 + 3;
    __syncthreads();

    if (tid < NTILE) g_cnt[b * NTILE + tid] = incl[(tid + 1) * 16 - 1];

    const int nv = total_s;
    const int nvp = (nv + 63) & ~63;
    for (int r = tid; r < nvp; r += 256) {
        const bool valid = (r < nv);
        const int orig = valid ? list[r] : 0;
        g_kidx[b * T_ + r] = valid ? orig : PAD_IDX;
        uint4* dst = (uint4*)(g_xc + ((size_t)b * T_ + r) * C_);
        if (valid) {
            const uint4* src = (const uint4*)(g_xh + ((size_t)b * T_ + orig) * C_);
#pragma unroll 8
            for (int i = 0; i < 32; i++) dst[i] = src[i];
        } else {
            const uint4 z = make_uint4(0, 0, 0, 0);
#pragma unroll 8
            for (int i = 0; i < 32; i++) dst[i] = z;
        }
    }
}

// ---------------------------------------------------------------------------
// Kernel 2: flash attention over COMPACTED keys. fp16 mma, register P,
// in-register online softmax, unified mask = (orig_idx <= q_row).
// Heavy-first launch. 128 thr, 2 CTAs/SM.
// ---------------------------------------------------------------------------
__global__ void __launch_bounds__(128, 2)
attn_kernel(const float* __restrict__ gamma, const float* __restrict__ beta)
{
    extern __shared__ char smc[];
    float* smf = (float*)smc;
    const uint32_t sb = smem_u32(smc);

    const int qt   = 15 - blockIdx.y;        // heavy tiles first
    const int b    = blockIdx.x;
    const int tid  = threadIdx.x;
    const int lane = tid & 31;
    const int w    = tid >> 5;
    const int jj   = lane & 3;
    const int g8   = lane >> 2;
    const int l15  = lane & 15;
    const int lh   = lane >> 4;
    const int q0   = qt * BR;
    const int row0 = w * 16 + g8;
    const int grow0 = q0 + row0, grow1 = grow0 + 8;
    const __half* xb  = g_xh + (size_t)b * T_ * C_;   // queries
    const __half* xcb = g_xc + (size_t)b * T_ * C_;   // compacted keys
    const int*    kib = g_kidx + b * T_;

    const int cnt    = g_cnt[b * NTILE + qt];
    const int ntiles = (cnt + 63) >> 6;

    const uint32_t aQ = sb + OF_Q + (uint32_t)(w * 16 + l15) * 528 + lh * 16;

    // Prefetch Q (+ compacted key tile 0 if any)
#pragma unroll
    for (int it = 0; it < 16; it++) {
        int idx = tid + it * 128;
        int r = idx >> 5, g = idx & 31;
        cp16(sb + OF_Q + r * 528 + g * 16, xb + (size_t)(q0 + r) * C_ + g * 8);
    }
    if (ntiles > 0) {
#pragma unroll
        for (int it = 0; it < 16; it++) {
            int idx = tid + it * 128;
            int r = idx >> 5, g = idx & 31;
            cp16(sb + OF_X0 + r * 528 + g * 16, xcb + (size_t)r * C_ + g * 8);
        }
    }
    asm volatile("cp.async.commit_group;");

    float Oacc[32][4];
#pragma unroll
    for (int i = 0; i < 32; i++)
#pragma unroll
        for (int e = 0; e < 4; e++) Oacc[i][e] = 0.f;
    float m0 = -INFINITY, m1 = -INFINITY, l0 = 0.f, l1 = 0.f;

    for (int st = 0; st < ntiles; st++) {
        const uint32_t Xoff = (st & 1) ? OF_X1 : OF_X0;
        const int s0 = st * BR;

        asm volatile("cp.async.wait_group 0;");
        __syncthreads();                      // X[st] visible; other buffer free

        if (st + 1 < ntiles) {                // prefetch next compacted tile
            const uint32_t Xn = ((st + 1) & 1) ? OF_X1 : OF_X0;
            const __half* src = xcb + (size_t)(st + 1) * BR * C_;
#pragma unroll
            for (int it = 0; it < 16; it++) {
                int idx = tid + it * 128;
                int r = idx >> 5, g = idx & 31;
                cp16(sb + Xn + r * 528 + g * 16, src + (size_t)r * C_ + g * 8);
            }
            asm volatile("cp.async.commit_group;");
        }

        // orig indices for my 16 S-columns (causal+padding mask unified)
        int2 kiv[8];
#pragma unroll
        for (int nt = 0; nt < 8; nt++)
            kiv[nt] = *(const int2*)(kib + s0 + nt * 8 + 2 * jj);

        // ---- Stage A: S = Q Kc^T, warp tile 16x64 ----
        uint32_t aK[4];
#pragma unroll
        for (int nb = 0; nb < 4; nb++)
            aK[nb] = sb + Xoff + (uint32_t)(nb * 16 + (lane & 7) + lh * 8) * 528
                     + ((lane >> 3) & 1) * 16;

        float sacc[8][4];
#pragma unroll
        for (int nt = 0; nt < 8; nt++)
#pragma unroll
            for (int e = 0; e < 4; e++) sacc[nt][e] = 0.f;

#pragma unroll
        for (int k = 0; k < 16; k++) {
            uint32_t a0, a1, a2, a3;
            ldsm4(a0, a1, a2, a3, aQ + k * 32);
#pragma unroll
            for (int nb = 0; nb < 4; nb++) {
                uint32_t b0, b1, b2, b3;
                ldsm4(b0, b1, b2, b3, aK[nb] + k * 32);
                mma_f16(sacc[2 * nb],     a0, a1, a2, a3, b0, b1);
                mma_f16(sacc[2 * nb + 1], a0, a1, a2, a3, b2, b3);
            }
        }

        // ---- Mask + in-register online softmax (quad shuffles only) ----
#pragma unroll
        for (int nt = 0; nt < 8; nt++) {
#pragma unroll
            for (int e = 0; e < 2; e++) {
                const int ki = e ? kiv[nt].y : kiv[nt].x;
                sacc[nt][e]     = (ki <= grow0) ? sacc[nt][e] * 0.0625f     : -INFINITY;
                sacc[nt][2 + e] = (ki <= grow1) ? sacc[nt][2 + e] * 0.0625f : -INFINITY;
            }
        }
        float mt0 = -INFINITY, mt1 = -INFINITY;
#pragma unroll
        for (int nt = 0; nt < 8; nt++) {
            mt0 = fmaxf(mt0, fmaxf(sacc[nt][0], sacc[nt][1]));
            mt1 = fmaxf(mt1, fmaxf(sacc[nt][2], sacc[nt][3]));
        }
        mt0 = fmaxf(mt0, __shfl_xor_sync(0xffffffffu, mt0, 1));
        mt0 = fmaxf(mt0, __shfl_xor_sync(0xffffffffu, mt0, 2));
        mt1 = fmaxf(mt1, __shfl_xor_sync(0xffffffffu, mt1, 1));
        mt1 = fmaxf(mt1, __shfl_xor_sync(0xffffffffu, mt1, 2));
        const float mn0 = fmaxf(m0, mt0), mn1 = fmaxf(m1, mt1);
        const float al0 = (m0 == -INFINITY) ? 0.f : __expf(m0 - mn0);
        const float al1 = (m1 == -INFINITY) ? 0.f : __expf(m1 - mn1);

        float p0[8][2], p1[8][2], sum0 = 0.f, sum1 = 0.f;
#pragma unroll
        for (int nt = 0; nt < 8; nt++) {
#pragma unroll
            for (int e = 0; e < 2; e++) {
                float a = sacc[nt][e],     pa = (a == -INFINITY) ? 0.f : __expf(a - mn0);
                float c = sacc[nt][2 + e], pc = (c == -INFINITY) ? 0.f : __expf(c - mn1);
                p0[nt][e] = pa; sum0 += pa;
                p1[nt][e] = pc; sum1 += pc;
            }
        }
        sum0 += __shfl_xor_sync(0xffffffffu, sum0, 1);
        sum0 += __shfl_xor_sync(0xffffffffu, sum0, 2);
        sum1 += __shfl_xor_sync(0xffffffffu, sum1, 1);
        sum1 += __shfl_xor_sync(0xffffffffu, sum1, 2);
        l0 = l0 * al0 + sum0;  m0 = mn0;
        l1 = l1 * al1 + sum1;  m1 = mn1;

        // rescale O accumulators
#pragma unroll
        for (int i = 0; i < 32; i++) {
            Oacc[i][0] *= al0; Oacc[i][1] *= al0;
            Oacc[i][2] *= al1; Oacc[i][3] *= al1;
        }

        // pack P into A-fragments
        uint32_t pA[4][4];
#pragma unroll
        for (int kb = 0; kb < 4; kb++) {
            pA[kb][0] = packh2(p0[2 * kb][0],     p0[2 * kb][1]);
            pA[kb][1] = packh2(p1[2 * kb][0],     p1[2 * kb][1]);
            pA[kb][2] = packh2(p0[2 * kb + 1][0], p0[2 * kb + 1][1]);
            pA[kb][3] = packh2(p1[2 * kb + 1][0], p1[2 * kb + 1][1]);
        }

        // ---- Stage B: O += P @ Xc, warp tile 16x256 ----
        const uint32_t aXb = sb + Xoff + (uint32_t)l15 * 528 + lh * 16;
#pragma unroll
        for (int ks = 0; ks < 4; ks++) {
#pragma unroll
            for (int n16 = 0; n16 < 16; n16++) {
                uint32_t x0, x1, x2, x3;
                ldsm4t(x0, x1, x2, x3, aXb + ks * 16 * 528 + n16 * 32);
                mma_f16(Oacc[2 * n16],     pA[ks][0], pA[ks][1], pA[ks][2], pA[ks][3], x0, x1);
                mma_f16(Oacc[2 * n16 + 1], pA[ks][0], pA[ks][1], pA[ks][2], pA[ks][3], x2, x3);
            }
        }
    }
    asm volatile("cp.async.wait_group 0;");    // drain (covers ntiles==0 path)

    // ---- per-CTA colsum reduction (pre-scaled) into never-aliased smem ----
    {
        float s0 = 0.f, s1 = 0.f;
#pragma unroll
        for (int i = 0; i < 16; i++) {
            s0 += g_cs16[(b * 16 + i) * C_ + tid];
            s1 += g_cs16[(b * 16 + i) * C_ + tid + 128];
        }
        smf[OF_CS / 4 + tid]       = s0 * (1.f / 1024.f);
        smf[OF_CS / 4 + tid + 128] = s1 * (1.f / 1024.f);
    }

    // ---- Epilogue: normalize / degenerate fixup -> Os staging ----
    __syncthreads();
    float* Os = smf;
    const float* csum = smf + OF_CS / 4;
    {
        const bool d0 = (l0 == 0.f), d1 = (l1 == 0.f);
        const float inv0 = d0 ? 0.f : (1.f / l0);
        const float inv1 = d1 ? 0.f : (1.f / l1);
#pragma unroll
        for (int nt2 = 0; nt2 < 32; nt2++)
#pragma unroll
            for (int e = 0; e < 2; e++) {
                const int c = nt2 * 8 + 2 * jj + e;
                const float cm = csum[c];
                Os[row0 * OSS + c]       = d0 ? cm : Oacc[nt2][e] * inv0;
                Os[(row0 + 8) * OSS + c] = d1 ? cm : Oacc[nt2][2 + e] * inv1;
            }
    }
    __syncthreads();

    // ---- LayerNorm stats (2 threads per row) ----
    {
        const int r = tid >> 1, hf = tid & 1;
        const float* row = Os + r * OSS + hf * 128;
        float s1 = 0.f;
#pragma unroll 8
        for (int c = 0; c < 128; c++) s1 += row[c];
        s1 += __shfl_xor_sync(0xffffffffu, s1, 1);
        const float mu = s1 * (1.f / 256.f);
        float s2 = 0.f;
#pragma unroll 8
        for (int c = 0; c < 128; c++) { float d = row[c] - mu; s2 += d * d; }
        s2 += __shfl_xor_sync(0xffffffffu, s2, 1);
        const float rstd = rsqrtf(s2 * (1.f / 256.f) + 1e-9f);
        if (hf == 0) { smf[OF_MU / 4 + r] = mu; smf[OF_RS / 4 + r] = rstd; }
    }
    __syncthreads();

    // ---- Column partials (each thread: cols tid, tid+128) ----
    {
        float acc0 = 0.f, acc1 = 0.f;
#pragma unroll 4
        for (int r = 0; r < BR; r++) {
            const float muv = smf[OF_MU / 4 + r], rsv = smf[OF_RS / 4 + r];
            acc0 += (Os[r * OSS + tid]       - muv) * rsv;
            acc1 += (Os[r * OSS + tid + 128] - muv) * rsv;
        }
        float* gp = g_part + (size_t)(b * NTILE + qt) * C_;
        gp[tid]       = gamma[tid]       * acc0 + 64.f * beta[tid];
        gp[tid + 128] = gamma[tid + 128] * acc1 + 64.f * beta[tid + 128];
    }
}

// ---------------------------------------------------------------------------
// Kernel 3: reduce q-tile partials -> mean over T
// ---------------------------------------------------------------------------
__global__ void finalize_kernel(float* __restrict__ out) {
    const int b = blockIdx.x, c = threadIdx.x;
    float s = 0.f;
#pragma unroll
    for (int qtl = 0; qtl < NTILE; qtl++) s += g_part[(b * NTILE + qtl) * C_ + c];
    out[b * C_ + c] = s * (1.f / 1024.f);
}

// ---------------------------------------------------------------------------
extern "C" void kernel_launch(void* const* d_in, const int* in_sizes, int n_in,
                              void* d_out, int out_size)
{
    const float* x     = (const float*)d_in[0];
    const int*   km    = (const int*)  d_in[1];
    const float* gamma = (const float*)d_in[2];
    const float* beta  = (const float*)d_in[3];
    float*       out   = (float*)d_out;

    cudaFuncSetAttribute(attn_kernel,
                         cudaFuncAttributeMaxDynamicSharedMemorySize, SMEM_TOTAL);

    prep_kernel<<<dim3(B_, 16), 256>>>(x);
    compact_kernel<<<B_, 256>>>(km);
    attn_kernel<<<dim3(B_, NTILE), 128, SMEM_TOTAL>>>(gamma, beta);
    finalize_kernel<<<B_, 256>>>(out);
}

// round 14
// speedup vs baseline: 1.3645x; 1.1043x over previous
#include <cuda_runtime.h>
#include <cuda_fp16.h>
#include <math.h>
#include <stdint.h>

// Problem constants
#define B_  64
#define T_  1024
#define C_  256
#define BR  64               // query rows per CTA (= key tile)
#define NTILE (T_ / BR)      // 16
#define OSS 260              // final O staging stride (floats)

// SMEM byte offsets (per CTA ~100.5 KB -> 2 CTAs/SM)
#define OF_Q   0             // 64 rows x 528B
#define OF_X0  33792         // 64 rows x 528B (double-buffered compacted K=V)
#define OF_X1  67584
#define OF_MU  101376        // mu[64]
#define OF_RS  101632        // rstd[64]
#define OF_CS  101888        // colsum/1024 [256] (never aliased)
#define SMEM_TOTAL 102912

#define PAD_IDX 0x3FFFFFFF

// Device scratch
__device__ __half g_xh[B_ * T_ * C_];     // fp16 copy of x
__device__ __half g_xc[B_ * T_ * C_];     // compacted valid keys (fp16), zero-padded
__device__ int    g_kidx[B_ * T_];        // orig index per compacted key (pad: PAD_IDX)
__device__ int    g_cnt[B_ * NTILE];      // # valid keys with idx < (qt+1)*64
__device__ float  g_cs16[B_ * 16 * C_];   // colsum partials
__device__ float  g_colsum[B_ * C_];      // pre-scaled colsum/1024
__device__ float  g_part[B_ * NTILE * C_];

// ---------------------------------------------------------------------------
static __device__ __forceinline__ uint32_t smem_u32(const void* p) {
    return (uint32_t)__cvta_generic_to_shared(p);
}
static __device__ __forceinline__ void cp16(uint32_t dst, const void* src) {
    asm volatile("cp.async.cg.shared.global [%0], [%1], 16;" :: "r"(dst), "l"(src));
}
static __device__ __forceinline__ void ldsm4(
    uint32_t& r0, uint32_t& r1, uint32_t& r2, uint32_t& r3, uint32_t a)
{
    asm volatile("ldmatrix.sync.aligned.m8n8.x4.shared.b16 {%0,%1,%2,%3}, [%4];"
                 : "=r"(r0), "=r"(r1), "=r"(r2), "=r"(r3) : "r"(a));
}
static __device__ __forceinline__ void ldsm4t(
    uint32_t& r0, uint32_t& r1, uint32_t& r2, uint32_t& r3, uint32_t a)
{
    asm volatile("ldmatrix.sync.aligned.m8n8.x4.trans.shared.b16 {%0,%1,%2,%3}, [%4];"
                 : "=r"(r0), "=r"(r1), "=r"(r2), "=r"(r3) : "r"(a));
}
static __device__ __forceinline__ void mma_f16(
    float* d, uint32_t a0, uint32_t a1, uint32_t a2, uint32_t a3,
    uint32_t b0, uint32_t b1)
{
    asm volatile(
        "mma.sync.aligned.m16n8k16.row.col.f32.f16.f16.f32 "
        "{%0,%1,%2,%3},{%4,%5,%6,%7},{%8,%9},{%0,%1,%2,%3};"
        : "+f"(d[0]), "+f"(d[1]), "+f"(d[2]), "+f"(d[3])
        : "r"(a0), "r"(a1), "r"(a2), "r"(a3), "r"(b0), "r"(b1));
}
static __device__ __forceinline__ uint32_t packh2(float x, float y) {
    __half2 h = __floats2half2_rn(x, y);
    return *(uint32_t*)&h;
}

// ---------------------------------------------------------------------------
// Kernel 1: fp16 copy of x + exact fp32 colsum partials
// ---------------------------------------------------------------------------
__global__ void prep_kernel(const float* __restrict__ x) {
    const int b = blockIdx.x, ch = blockIdx.y, c = threadIdx.x;
    const size_t base = ((size_t)b * T_ + (size_t)ch * 64) * C_ + c;
    const float* xp = x + base;
    __half* op = g_xh + base;
    float s = 0.f;
#pragma unroll 8
    for (int t = 0; t < 64; t++) {
        float v = xp[(size_t)t * C_];
        s += v;
        op[(size_t)t * C_] = __float2half_rn(v);
    }
    g_cs16[(b * 16 + ch) * C_ + c] = s;
}

// ---------------------------------------------------------------------------
// Kernel 1b: per-batch scan (prefix-sum of key mask) + colsum reduce.
// One CTA (256 thr) per batch; light (~2us).
// ---------------------------------------------------------------------------
__global__ void scan_kernel(const int* __restrict__ km) {
    __shared__ int list[T_];
    __shared__ int wsum[8];
    __shared__ int incl[256];
    __shared__ int total_s;

    const int b = blockIdx.x, tid = threadIdx.x;
    const int lane = tid & 31, wp = tid >> 5;

    int4 f = ((const int4*)(km + b * T_))[tid];   // flags for keys 4tid..4tid+3
    int c0 = (f.x != 0), c1 = (f.y != 0), c2 = (f.z != 0), c3 = (f.w != 0);
    int cnt4 = c0 + c1 + c2 + c3;

    int v = cnt4;
#pragma unroll
    for (int off = 1; off < 32; off <<= 1) {
        int n = __shfl_up_sync(0xffffffffu, v, off);
        if (lane >= off) v += n;
    }
    if (lane == 31) wsum[wp] = v;
    __syncthreads();
    if (tid == 0) {
        int running = 0;
#pragma unroll
        for (int i = 0; i < 8; i++) { int t = wsum[i]; wsum[i] = running; running += t; }
        total_s = running;
    }
    __syncthreads();
    const int excl = v - cnt4 + wsum[wp];
    incl[tid] = excl + cnt4;

    int base = excl;
    const int t0 = tid * 4;
    if (c0) list[base++] = t0;
    if (c1) list[base++] = t0 + 1;
    if (c2) list[base++] = t0 + 2;
    if (c3) list[base++] = t0 + 3;
    __syncthreads();

    if (tid < NTILE) g_cnt[b * NTILE + tid] = incl[(tid + 1) * 16 - 1];

    const int nv = total_s;
    const int nvp = (nv + 63) & ~63;
    for (int r = tid; r < nvp; r += 256)
        g_kidx[b * T_ + r] = (r < nv) ? list[r] : PAD_IDX;

    // colsum reduce (pre-scaled), order i=0..15 preserved
    float s = 0.f;
#pragma unroll
    for (int i = 0; i < 16; i++) s += g_cs16[(b * 16 + i) * C_ + tid];
    g_colsum[b * C_ + tid] = s * (1.f / 1024.f);
}

// ---------------------------------------------------------------------------
// Kernel 1c: full-chip gather of compacted key rows. grid (B_, 16), 256 thr.
// CTA (b, ch) handles compacted rows ch*64 .. ch*64+63 (skip beyond pad).
// Thread = (row within 64) x (128B chunk).
// ---------------------------------------------------------------------------
__global__ void gather_kernel() {
    const int b = blockIdx.x, ch = blockIdx.y, tid = threadIdx.x;
    const int nv = g_cnt[b * NTILE + NTILE - 1];
    const int nvp = (nv + 63) & ~63;
    const int r0 = ch * 64;
    if (r0 >= nvp) return;                    // CTA-uniform exit

    const int row = r0 + (tid >> 2);
    const int chunk = tid & 3;                // 128B chunk within the 512B row
    const int orig = g_kidx[b * T_ + row];
    uint4* dst = (uint4*)(g_xc + ((size_t)b * T_ + row) * C_ + chunk * 64);
    if (orig != PAD_IDX) {
        const uint4* src = (const uint4*)(g_xh + ((size_t)b * T_ + orig) * C_ + chunk * 64);
#pragma unroll
        for (int i = 0; i < 8; i++) dst[i] = src[i];
    } else {
        const uint4 z = make_uint4(0, 0, 0, 0);
#pragma unroll
        for (int i = 0; i < 8; i++) dst[i] = z;
    }
}

// ---------------------------------------------------------------------------
// Kernel 2: flash attention over COMPACTED keys. fp16 mma, register P,
// in-register online softmax, unified mask (orig_idx <= q_row).
// Heavy-first launch. 128 thr, 2 CTAs/SM.
// ---------------------------------------------------------------------------
__global__ void __launch_bounds__(128, 2)
attn_kernel(const float* __restrict__ gamma, const float* __restrict__ beta)
{
    extern __shared__ char smc[];
    float* smf = (float*)smc;
    const uint32_t sb = smem_u32(smc);

    const int qt   = 15 - blockIdx.y;        // heavy tiles first
    const int b    = blockIdx.x;
    const int tid  = threadIdx.x;
    const int lane = tid & 31;
    const int w    = tid >> 5;
    const int jj   = lane & 3;
    const int g8   = lane >> 2;
    const int l15  = lane & 15;
    const int lh   = lane >> 4;
    const int q0   = qt * BR;
    const int row0 = w * 16 + g8;
    const int grow0 = q0 + row0, grow1 = grow0 + 8;
    const __half* xb  = g_xh + (size_t)b * T_ * C_;
    const __half* xcb = g_xc + (size_t)b * T_ * C_;
    const int*    kib = g_kidx + b * T_;

    const int cnt    = g_cnt[b * NTILE + qt];
    const int ntiles = (cnt + 63) >> 6;

    const uint32_t aQ = sb + OF_Q + (uint32_t)(w * 16 + l15) * 528 + lh * 16;

    // Prefetch Q (+ key tile 0 if any)
#pragma unroll
    for (int it = 0; it < 16; it++) {
        int idx = tid + it * 128;
        int r = idx >> 5, g = idx & 31;
        cp16(sb + OF_Q + r * 528 + g * 16, xb + (size_t)(q0 + r) * C_ + g * 8);
    }
    if (ntiles > 0) {
#pragma unroll
        for (int it = 0; it < 16; it++) {
            int idx = tid + it * 128;
            int r = idx >> 5, g = idx & 31;
            cp16(sb + OF_X0 + r * 528 + g * 16, xcb + (size_t)r * C_ + g * 8);
        }
    }
    asm volatile("cp.async.commit_group;");

    float Oacc[32][4];
#pragma unroll
    for (int i = 0; i < 32; i++)
#pragma unroll
        for (int e = 0; e < 4; e++) Oacc[i][e] = 0.f;
    float m0 = -INFINITY, m1 = -INFINITY, l0 = 0.f, l1 = 0.f;

    for (int st = 0; st < ntiles; st++) {
        const uint32_t Xoff = (st & 1) ? OF_X1 : OF_X0;
        const int s0 = st * BR;

        asm volatile("cp.async.wait_group 0;");
        __syncthreads();                      // X[st] visible; other buffer free

        if (st + 1 < ntiles) {
            const uint32_t Xn = ((st + 1) & 1) ? OF_X1 : OF_X0;
            const __half* src = xcb + (size_t)(st + 1) * BR * C_;
#pragma unroll
            for (int it = 0; it < 16; it++) {
                int idx = tid + it * 128;
                int r = idx >> 5, g = idx & 31;
                cp16(sb + Xn + r * 528 + g * 16, src + (size_t)r * C_ + g * 8);
            }
            asm volatile("cp.async.commit_group;");
        }

        int2 kiv[8];
#pragma unroll
        for (int nt = 0; nt < 8; nt++)
            kiv[nt] = *(const int2*)(kib + s0 + nt * 8 + 2 * jj);

        // ---- Stage A: S = Q Kc^T, warp tile 16x64 ----
        uint32_t aK[4];
#pragma unroll
        for (int nb = 0; nb < 4; nb++)
            aK[nb] = sb + Xoff + (uint32_t)(nb * 16 + (lane & 7) + lh * 8) * 528
                     + ((lane >> 3) & 1) * 16;

        float sacc[8][4];
#pragma unroll
        for (int nt = 0; nt < 8; nt++)
#pragma unroll
            for (int e = 0; e < 4; e++) sacc[nt][e] = 0.f;

#pragma unroll
        for (int k = 0; k < 16; k++) {
            uint32_t a0, a1, a2, a3;
            ldsm4(a0, a1, a2, a3, aQ + k * 32);
#pragma unroll
            for (int nb = 0; nb < 4; nb++) {
                uint32_t b0, b1, b2, b3;
                ldsm4(b0, b1, b2, b3, aK[nb] + k * 32);
                mma_f16(sacc[2 * nb],     a0, a1, a2, a3, b0, b1);
                mma_f16(sacc[2 * nb + 1], a0, a1, a2, a3, b2, b3);
            }
        }

        // ---- Mask + in-register online softmax ----
#pragma unroll
        for (int nt = 0; nt < 8; nt++) {
#pragma unroll
            for (int e = 0; e < 2; e++) {
                const int ki = e ? kiv[nt].y : kiv[nt].x;
                sacc[nt][e]     = (ki <= grow0) ? sacc[nt][e] * 0.0625f     : -INFINITY;
                sacc[nt][2 + e] = (ki <= grow1) ? sacc[nt][2 + e] * 0.0625f : -INFINITY;
            }
        }
        float mt0 = -INFINITY, mt1 = -INFINITY;
#pragma unroll
        for (int nt = 0; nt < 8; nt++) {
            mt0 = fmaxf(mt0, fmaxf(sacc[nt][0], sacc[nt][1]));
            mt1 = fmaxf(mt1, fmaxf(sacc[nt][2], sacc[nt][3]));
        }
        mt0 = fmaxf(mt0, __shfl_xor_sync(0xffffffffu, mt0, 1));
        mt0 = fmaxf(mt0, __shfl_xor_sync(0xffffffffu, mt0, 2));
        mt1 = fmaxf(mt1, __shfl_xor_sync(0xffffffffu, mt1, 1));
        mt1 = fmaxf(mt1, __shfl_xor_sync(0xffffffffu, mt1, 2));
        const float mn0 = fmaxf(m0, mt0), mn1 = fmaxf(m1, mt1);
        const float al0 = (m0 == -INFINITY) ? 0.f : __expf(m0 - mn0);
        const float al1 = (m1 == -INFINITY) ? 0.f : __expf(m1 - mn1);

        float p0[8][2], p1[8][2], sum0 = 0.f, sum1 = 0.f;
#pragma unroll
        for (int nt = 0; nt < 8; nt++) {
#pragma unroll
            for (int e = 0; e < 2; e++) {
                float a = sacc[nt][e],     pa = (a == -INFINITY) ? 0.f : __expf(a - mn0);
                float c = sacc[nt][2 + e], pc = (c == -INFINITY) ? 0.f : __expf(c - mn1);
                p0[nt][e] = pa; sum0 += pa;
                p1[nt][e] = pc; sum1 += pc;
            }
        }
        sum0 += __shfl_xor_sync(0xffffffffu, sum0, 1);
        sum0 += __shfl_xor_sync(0xffffffffu, sum0, 2);
        sum1 += __shfl_xor_sync(0xffffffffu, sum1, 1);
        sum1 += __shfl_xor_sync(0xffffffffu, sum1, 2);
        l0 = l0 * al0 + sum0;  m0 = mn0;
        l1 = l1 * al1 + sum1;  m1 = mn1;

#pragma unroll
        for (int i = 0; i < 32; i++) {
            Oacc[i][0] *= al0; Oacc[i][1] *= al0;
            Oacc[i][2] *= al1; Oacc[i][3] *= al1;
        }

        uint32_t pA[4][4];
#pragma unroll
        for (int kb = 0; kb < 4; kb++) {
            pA[kb][0] = packh2(p0[2 * kb][0],     p0[2 * kb][1]);
            pA[kb][1] = packh2(p1[2 * kb][0],     p1[2 * kb][1]);
            pA[kb][2] = packh2(p0[2 * kb + 1][0], p0[2 * kb + 1][1]);
            pA[kb][3] = packh2(p1[2 * kb + 1][0], p1[2 * kb + 1][1]);
        }

        // ---- Stage B: O += P @ Xc, warp tile 16x256 ----
        const uint32_t aXb = sb + Xoff + (uint32_t)l15 * 528 + lh * 16;
#pragma unroll
        for (int ks = 0; ks < 4; ks++) {
#pragma unroll
            for (int n16 = 0; n16 < 16; n16++) {
                uint32_t x0, x1, x2, x3;
                ldsm4t(x0, x1, x2, x3, aXb + ks * 16 * 528 + n16 * 32);
                mma_f16(Oacc[2 * n16],     pA[ks][0], pA[ks][1], pA[ks][2], pA[ks][3], x0, x1);
                mma_f16(Oacc[2 * n16 + 1], pA[ks][0], pA[ks][1], pA[ks][2], pA[ks][3], x2, x3);
            }
        }
    }
    asm volatile("cp.async.wait_group 0;");    // drain (covers ntiles==0)

    // ---- colsum (pre-scaled, pre-reduced) -> never-aliased smem ----
    smf[OF_CS / 4 + tid]       = g_colsum[b * C_ + tid];
    smf[OF_CS / 4 + tid + 128] = g_colsum[b * C_ + tid + 128];

    // ---- Epilogue: normalize / degenerate fixup -> Os staging ----
    __syncthreads();
    float* Os = smf;
    const float* csum = smf + OF_CS / 4;
    {
        const bool d0 = (l0 == 0.f), d1 = (l1 == 0.f);
        const float inv0 = d0 ? 0.f : (1.f / l0);
        const float inv1 = d1 ? 0.f : (1.f / l1);
#pragma unroll
        for (int nt2 = 0; nt2 < 32; nt2++)
#pragma unroll
            for (int e = 0; e < 2; e++) {
                const int c = nt2 * 8 + 2 * jj + e;
                const float cm = csum[c];
                Os[row0 * OSS + c]       = d0 ? cm : Oacc[nt2][e] * inv0;
                Os[(row0 + 8) * OSS + c] = d1 ? cm : Oacc[nt2][2 + e] * inv1;
            }
    }
    __syncthreads();

    // ---- LayerNorm stats (2 threads per row) ----
    {
        const int r = tid >> 1, hf = tid & 1;
        const float* row = Os + r * OSS + hf * 128;
        float s1 = 0.f;
#pragma unroll 8
        for (int c = 0; c < 128; c++) s1 += row[c];
        s1 += __shfl_xor_sync(0xffffffffu, s1, 1);
        const float mu = s1 * (1.f / 256.f);
        float s2 = 0.f;
#pragma unroll 8
        for (int c = 0; c < 128; c++) { float d = row[c] - mu; s2 += d * d; }
        s2 += __shfl_xor_sync(0xffffffffu, s2, 1);
        const float rstd = rsqrtf(s2 * (1.f / 256.f) + 1e-9f);
        if (hf == 0) { smf[OF_MU / 4 + r] = mu; smf[OF_RS / 4 + r] = rstd; }
    }
    __syncthreads();

    // ---- Column partials (each thread: cols tid, tid+128) ----
    {
        float acc0 = 0.f, acc1 = 0.f;
#pragma unroll 4
        for (int r = 0; r < BR; r++) {
            const float muv = smf[OF_MU / 4 + r], rsv = smf[OF_RS / 4 + r];
            acc0 += (Os[r * OSS + tid]       - muv) * rsv;
            acc1 += (Os[r * OSS + tid + 128] - muv) * rsv;
        }
        float* gp = g_part + (size_t)(b * NTILE + qt) * C_;
        gp[tid]       = gamma[tid]       * acc0 + 64.f * beta[tid];
        gp[tid + 128] = gamma[tid + 128] * acc1 + 64.f * beta[tid + 128];
    }
}

// ---------------------------------------------------------------------------
// Kernel 3: reduce q-tile partials -> mean over T
// ---------------------------------------------------------------------------
__global__ void finalize_kernel(float* __restrict__ out) {
    const int b = blockIdx.x, c = threadIdx.x;
    float s = 0.f;
#pragma unroll
    for (int qtl = 0; qtl < NTILE; qtl++) s += g_part[(b * NTILE + qtl) * C_ + c];
    out[b * C_ + c] = s * (1.f / 1024.f);
}

// ---------------------------------------------------------------------------
extern "C" void kernel_launch(void* const* d_in, const int* in_sizes, int n_in,
                              void* d_out, int out_size)
{
    const float* x     = (const float*)d_in[0];
    const int*   km    = (const int*)  d_in[1];
    const float* gamma = (const float*)d_in[2];
    const float* beta  = (const float*)d_in[3];
    float*       out   = (float*)d_out;

    cudaFuncSetAttribute(attn_kernel,
                         cudaFuncAttributeMaxDynamicSharedMemorySize, SMEM_TOTAL);

    prep_kernel<<<dim3(B_, 16), 256>>>(x);
    scan_kernel<<<B_, 256>>>(km);
    gather_kernel<<<dim3(B_, 16), 256>>>();
    attn_kernel<<<dim3(B_, NTILE), 128, SMEM_TOTAL>>>(gamma, beta);
    finalize_kernel<<<B_, 256>>>(out);
}

// round 15
// speedup vs baseline: 1.5076x; 1.1048x over previous
#include <cuda_runtime.h>
#include <cuda_fp16.h>
#include <math.h>
#include <stdint.h>

// Problem constants
#define B_  64
#define T_  1024
#define C_  256
#define BR  64               // query rows per CTA (= key tile)
#define NTILE (T_ / BR)      // 16
#define OSS 260              // final O staging stride (floats)

// SMEM byte offsets (per CTA ~100.5 KB -> 2 CTAs/SM)
#define OF_Q   0             // 64 rows x 528B
#define OF_X0  33792         // 64 rows x 528B (double-buffered gathered K=V)
#define OF_X1  67584
#define OF_MU  101376        // mu[64]
#define OF_RS  101632        // rstd[64]
#define OF_CS  101888        // colsum/1024 [256] (never aliased)
#define SMEM_TOTAL 102912

#define PAD_IDX 0x3FFFFFFF

// Device scratch
__device__ __half g_xh[B_ * T_ * C_];     // fp16 copy of x
__device__ __align__(512) __half g_zeroRow[C_];  // zero-init (static storage)
__device__ int    g_kidx[B_ * T_];        // orig index per compacted key slot
__device__ int    g_cnt[B_ * NTILE];      // # valid keys with idx < (qt+1)*64
__device__ int    g_done[B_];             // per-batch completion counter
__device__ float  g_cs64[B_ * 64 * C_];   // colsum partials (16-row groups)
__device__ float  g_colsum[B_ * C_];      // pre-scaled colsum/1024
__device__ float  g_part[B_ * NTILE * C_];

// ---------------------------------------------------------------------------
static __device__ __forceinline__ uint32_t smem_u32(const void* p) {
    return (uint32_t)__cvta_generic_to_shared(p);
}
static __device__ __forceinline__ void cp16(uint32_t dst, const void* src) {
    asm volatile("cp.async.cg.shared.global [%0], [%1], 16;" :: "r"(dst), "l"(src));
}
static __device__ __forceinline__ void ldsm4(
    uint32_t& r0, uint32_t& r1, uint32_t& r2, uint32_t& r3, uint32_t a)
{
    asm volatile("ldmatrix.sync.aligned.m8n8.x4.shared.b16 {%0,%1,%2,%3}, [%4];"
                 : "=r"(r0), "=r"(r1), "=r"(r2), "=r"(r3) : "r"(a));
}
static __device__ __forceinline__ void ldsm4t(
    uint32_t& r0, uint32_t& r1, uint32_t& r2, uint32_t& r3, uint32_t a)
{
    asm volatile("ldmatrix.sync.aligned.m8n8.x4.trans.shared.b16 {%0,%1,%2,%3}, [%4];"
                 : "=r"(r0), "=r"(r1), "=r"(r2), "=r"(r3) : "r"(a));
}
static __device__ __forceinline__ void mma_f16(
    float* d, uint32_t a0, uint32_t a1, uint32_t a2, uint32_t a3,
    uint32_t b0, uint32_t b1)
{
    asm volatile(
        "mma.sync.aligned.m16n8k16.row.col.f32.f16.f16.f32 "
        "{%0,%1,%2,%3},{%4,%5,%6,%7},{%8,%9},{%0,%1,%2,%3};"
        : "+f"(d[0]), "+f"(d[1]), "+f"(d[2]), "+f"(d[3])
        : "r"(a0), "r"(a1), "r"(a2), "r"(a3), "r"(b0), "r"(b1));
}
static __device__ __forceinline__ uint32_t packh2(float x, float y) {
    __half2 h = __floats2half2_rn(x, y);
    return *(uint32_t*)&h;
}

// ---------------------------------------------------------------------------
// Kernel 1: fp16 copy of x (vectorized) + fp32 colsum partials (16-row groups)
// grid (B_, 16), 256 thr: thread = (rowgroup rg of 16 rows) x (4 cols)
// ---------------------------------------------------------------------------
__global__ void prep_kernel(const float* __restrict__ x) {
    const int b = blockIdx.x, ch = blockIdx.y, tid = threadIdx.x;
    const int c4 = (tid & 63) * 4;
    const int rg = tid >> 6;                  // 0..3
    const size_t row0 = (size_t)b * T_ + ch * 64 + rg * 16;
    float s0 = 0.f, s1 = 0.f, s2 = 0.f, s3 = 0.f;
#pragma unroll
    for (int i = 0; i < 16; i++) {
        const float4 v = *(const float4*)(x + (row0 + i) * C_ + c4);
        s0 += v.x; s1 += v.y; s2 += v.z; s3 += v.w;
        __half2 h0 = __floats2half2_rn(v.x, v.y);
        __half2 h1 = __floats2half2_rn(v.z, v.w);
        *(uint2*)(g_xh + (row0 + i) * C_ + c4) =
            make_uint2(*(uint32_t*)&h0, *(uint32_t*)&h1);
    }
    *(float4*)(g_cs64 + ((size_t)(b * 64 + ch * 4 + rg)) * C_ + c4) =
        make_float4(s0, s1, s2, s3);
}

// ---------------------------------------------------------------------------
// Kernel 1b: per-batch scan (prefix-sum of key mask) + colsum reduce + done=0
// ---------------------------------------------------------------------------
__global__ void scan_kernel(const int* __restrict__ km) {
    __shared__ int list[T_];
    __shared__ int wsum[8];
    __shared__ int incl[256];
    __shared__ int total_s;

    const int b = blockIdx.x, tid = threadIdx.x;
    const int lane = tid & 31, wp = tid >> 5;

    if (tid == 0) g_done[b] = 0;

    int4 f = ((const int4*)(km + b * T_))[tid];
    int c0 = (f.x != 0), c1 = (f.y != 0), c2 = (f.z != 0), c3 = (f.w != 0);
    int cnt4 = c0 + c1 + c2 + c3;

    int v = cnt4;
#pragma unroll
    for (int off = 1; off < 32; off <<= 1) {
        int n = __shfl_up_sync(0xffffffffu, v, off);
        if (lane >= off) v += n;
    }
    if (lane == 31) wsum[wp] = v;
    __syncthreads();
    if (tid == 0) {
        int running = 0;
#pragma unroll
        for (int i = 0; i < 8; i++) { int t = wsum[i]; wsum[i] = running; running += t; }
        total_s = running;
    }
    __syncthreads();
    const int excl = v - cnt4 + wsum[wp];
    incl[tid] = excl + cnt4;

    int base = excl;
    const int t0 = tid * 4;
    if (c0) list[base++] = t0;
    if (c1) list[base++] = t0 + 1;
    if (c2) list[base++] = t0 + 2;
    if (c3) list[base++] = t0 + 3;
    __syncthreads();

    if (tid < NTILE) g_cnt[b * NTILE + tid] = incl[(tid + 1) * 16 - 1];

    const int nv = total_s;
    const int nvp = (nv + 63) & ~63;
    for (int r = tid; r < nvp; r += 256)
        g_kidx[b * T_ + r] = (r < nv) ? list[r] : PAD_IDX;

    // colsum reduce (pre-scaled), deterministic group order
    float s = 0.f;
#pragma unroll 8
    for (int i = 0; i < 64; i++) s += g_cs64[(size_t)(b * 64 + i) * C_ + tid];
    g_colsum[b * C_ + tid] = s * (1.f / 1024.f);
}

// ---------------------------------------------------------------------------
// Kernel 2: flash attention over compacted keys, gathered ON LOAD from g_xh
// via g_kidx (PAD rows -> zero row). fp16 mma, register P, in-register online
// softmax. Last CTA per batch performs the final time-mean reduction.
// Heavy-first launch. 128 thr, 2 CTAs/SM.
// ---------------------------------------------------------------------------
__global__ void __launch_bounds__(128, 2)
attn_kernel(const float* __restrict__ gamma, const float* __restrict__ beta,
            float* __restrict__ out)
{
    extern __shared__ char smc[];
    __shared__ int lastflag;
    float* smf = (float*)smc;
    const uint32_t sb = smem_u32(smc);

    const int qt   = 15 - blockIdx.y;        // heavy tiles first
    const int b    = blockIdx.x;
    const int tid  = threadIdx.x;
    const int lane = tid & 31;
    const int w    = tid >> 5;
    const int jj   = lane & 3;
    const int g8   = lane >> 2;
    const int l15  = lane & 15;
    const int lh   = lane >> 4;
    const int q0   = qt * BR;
    const int row0 = w * 16 + g8;
    const int grow0 = q0 + row0, grow1 = grow0 + 8;
    const __half* xb  = g_xh + (size_t)b * T_ * C_;
    const int*    kib = g_kidx + b * T_;

    const int cnt    = g_cnt[b * NTILE + qt];
    const int ntiles = (cnt + 63) >> 6;

    const uint32_t aQ = sb + OF_Q + (uint32_t)(w * 16 + l15) * 528 + lh * 16;

    // Prefetch Q (+ gathered key tile 0 if any)
#pragma unroll
    for (int it = 0; it < 16; it++) {
        int idx = tid + it * 128;
        int r = idx >> 5, g = idx & 31;
        cp16(sb + OF_Q + r * 528 + g * 16, xb + (size_t)(q0 + r) * C_ + g * 8);
    }
    if (ntiles > 0) {
#pragma unroll
        for (int it = 0; it < 16; it++) {
            int idx = tid + it * 128;
            int r = idx >> 5, g = idx & 31;
            const int orig = kib[r];
            const __half* src = (orig == PAD_IDX) ? g_zeroRow
                                                  : xb + (size_t)orig * C_;
            cp16(sb + OF_X0 + r * 528 + g * 16, src + g * 8);
        }
    }
    asm volatile("cp.async.commit_group;");

    float Oacc[32][4];
#pragma unroll
    for (int i = 0; i < 32; i++)
#pragma unroll
        for (int e = 0; e < 4; e++) Oacc[i][e] = 0.f;
    float m0 = -INFINITY, m1 = -INFINITY, l0 = 0.f, l1 = 0.f;

    for (int st = 0; st < ntiles; st++) {
        const uint32_t Xoff = (st & 1) ? OF_X1 : OF_X0;
        const int s0 = st * BR;

        asm volatile("cp.async.wait_group 0;");
        __syncthreads();                      // X[st] visible; other buffer free

        if (st + 1 < ntiles) {                // prefetch next gathered tile
            const uint32_t Xn = ((st + 1) & 1) ? OF_X1 : OF_X0;
            const int s0n = (st + 1) * BR;
#pragma unroll
            for (int it = 0; it < 16; it++) {
                int idx = tid + it * 128;
                int r = idx >> 5, g = idx & 31;
                const int orig = kib[s0n + r];
                const __half* src = (orig == PAD_IDX) ? g_zeroRow
                                                      : xb + (size_t)orig * C_;
                cp16(sb + Xn + r * 528 + g * 16, src + g * 8);
            }
            asm volatile("cp.async.commit_group;");
        }

        int2 kiv[8];
#pragma unroll
        for (int nt = 0; nt < 8; nt++)
            kiv[nt] = *(const int2*)(kib + s0 + nt * 8 + 2 * jj);

        // ---- Stage A: S = Q Kc^T, warp tile 16x64 ----
        uint32_t aK[4];
#pragma unroll
        for (int nb = 0; nb < 4; nb++)
            aK[nb] = sb + Xoff + (uint32_t)(nb * 16 + (lane & 7) + lh * 8) * 528
                     + ((lane >> 3) & 1) * 16;

        float sacc[8][4];
#pragma unroll
        for (int nt = 0; nt < 8; nt++)
#pragma unroll
            for (int e = 0; e < 4; e++) sacc[nt][e] = 0.f;

#pragma unroll
        for (int k = 0; k < 16; k++) {
            uint32_t a0, a1, a2, a3;
            ldsm4(a0, a1, a2, a3, aQ + k * 32);
#pragma unroll
            for (int nb = 0; nb < 4; nb++) {
                uint32_t b0, b1, b2, b3;
                ldsm4(b0, b1, b2, b3, aK[nb] + k * 32);
                mma_f16(sacc[2 * nb],     a0, a1, a2, a3, b0, b1);
                mma_f16(sacc[2 * nb + 1], a0, a1, a2, a3, b2, b3);
            }
        }

        // ---- Mask + in-register online softmax ----
#pragma unroll
        for (int nt = 0; nt < 8; nt++) {
#pragma unroll
            for (int e = 0; e < 2; e++) {
                const int ki = e ? kiv[nt].y : kiv[nt].x;
                sacc[nt][e]     = (ki <= grow0) ? sacc[nt][e] * 0.0625f     : -INFINITY;
                sacc[nt][2 + e] = (ki <= grow1) ? sacc[nt][2 + e] * 0.0625f : -INFINITY;
            }
        }
        float mt0 = -INFINITY, mt1 = -INFINITY;
#pragma unroll
        for (int nt = 0; nt < 8; nt++) {
            mt0 = fmaxf(mt0, fmaxf(sacc[nt][0], sacc[nt][1]));
            mt1 = fmaxf(mt1, fmaxf(sacc[nt][2], sacc[nt][3]));
        }
        mt0 = fmaxf(mt0, __shfl_xor_sync(0xffffffffu, mt0, 1));
        mt0 = fmaxf(mt0, __shfl_xor_sync(0xffffffffu, mt0, 2));
        mt1 = fmaxf(mt1, __shfl_xor_sync(0xffffffffu, mt1, 1));
        mt1 = fmaxf(mt1, __shfl_xor_sync(0xffffffffu, mt1, 2));
        const float mn0 = fmaxf(m0, mt0), mn1 = fmaxf(m1, mt1);
        const float al0 = (m0 == -INFINITY) ? 0.f : __expf(m0 - mn0);
        const float al1 = (m1 == -INFINITY) ? 0.f : __expf(m1 - mn1);

        float p0[8][2], p1[8][2], sum0 = 0.f, sum1 = 0.f;
#pragma unroll
        for (int nt = 0; nt < 8; nt++) {
#pragma unroll
            for (int e = 0; e < 2; e++) {
                float a = sacc[nt][e],     pa = (a == -INFINITY) ? 0.f : __expf(a - mn0);
                float c = sacc[nt][2 + e], pc = (c == -INFINITY) ? 0.f : __expf(c - mn1);
                p0[nt][e] = pa; sum0 += pa;
                p1[nt][e] = pc; sum1 += pc;
            }
        }
        sum0 += __shfl_xor_sync(0xffffffffu, sum0, 1);
        sum0 += __shfl_xor_sync(0xffffffffu, sum0, 2);
        sum1 += __shfl_xor_sync(0xffffffffu, sum1, 1);
        sum1 += __shfl_xor_sync(0xffffffffu, sum1, 2);
        l0 = l0 * al0 + sum0;  m0 = mn0;
        l1 = l1 * al1 + sum1;  m1 = mn1;

#pragma unroll
        for (int i = 0; i < 32; i++) {
            Oacc[i][0] *= al0; Oacc[i][1] *= al0;
            Oacc[i][2] *= al1; Oacc[i][3] *= al1;
        }

        uint32_t pA[4][4];
#pragma unroll
        for (int kb = 0; kb < 4; kb++) {
            pA[kb][0] = packh2(p0[2 * kb][0],     p0[2 * kb][1]);
            pA[kb][1] = packh2(p1[2 * kb][0],     p1[2 * kb][1]);
            pA[kb][2] = packh2(p0[2 * kb + 1][0], p0[2 * kb + 1][1]);
            pA[kb][3] = packh2(p1[2 * kb + 1][0], p1[2 * kb + 1][1]);
        }

        // ---- Stage B: O += P @ Xc, warp tile 16x256 ----
        const uint32_t aXb = sb + Xoff + (uint32_t)l15 * 528 + lh * 16;
#pragma unroll
        for (int ks = 0; ks < 4; ks++) {
#pragma unroll
            for (int n16 = 0; n16 < 16; n16++) {
                uint32_t x0, x1, x2, x3;
                ldsm4t(x0, x1, x2, x3, aXb + ks * 16 * 528 + n16 * 32);
                mma_f16(Oacc[2 * n16],     pA[ks][0], pA[ks][1], pA[ks][2], pA[ks][3], x0, x1);
                mma_f16(Oacc[2 * n16 + 1], pA[ks][0], pA[ks][1], pA[ks][2], pA[ks][3], x2, x3);
            }
        }
    }
    asm volatile("cp.async.wait_group 0;");    // drain (covers ntiles==0)

    // ---- colsum (pre-scaled, pre-reduced) -> never-aliased smem ----
    smf[OF_CS / 4 + tid]       = g_colsum[b * C_ + tid];
    smf[OF_CS / 4 + tid + 128] = g_colsum[b * C_ + tid + 128];

    // ---- Epilogue: normalize / degenerate fixup -> Os staging ----
    __syncthreads();
    float* Os = smf;
    const float* csum = smf + OF_CS / 4;
    {
        const bool d0 = (l0 == 0.f), d1 = (l1 == 0.f);
        const float inv0 = d0 ? 0.f : (1.f / l0);
        const float inv1 = d1 ? 0.f : (1.f / l1);
#pragma unroll
        for (int nt2 = 0; nt2 < 32; nt2++)
#pragma unroll
            for (int e = 0; e < 2; e++) {
                const int c = nt2 * 8 + 2 * jj + e;
                const float cm = csum[c];
                Os[row0 * OSS + c]       = d0 ? cm : Oacc[nt2][e] * inv0;
                Os[(row0 + 8) * OSS + c] = d1 ? cm : Oacc[nt2][2 + e] * inv1;
            }
    }
    __syncthreads();

    // ---- LayerNorm stats (2 threads per row) ----
    {
        const int r = tid >> 1, hf = tid & 1;
        const float* row = Os + r * OSS + hf * 128;
        float s1 = 0.f;
#pragma unroll 8
        for (int c = 0; c < 128; c++) s1 += row[c];
        s1 += __shfl_xor_sync(0xffffffffu, s1, 1);
        const float mu = s1 * (1.f / 256.f);
        float s2 = 0.f;
#pragma unroll 8
        for (int c = 0; c < 128; c++) { float d = row[c] - mu; s2 += d * d; }
        s2 += __shfl_xor_sync(0xffffffffu, s2, 1);
        const float rstd = rsqrtf(s2 * (1.f / 256.f) + 1e-9f);
        if (hf == 0) { smf[OF_MU / 4 + r] = mu; smf[OF_RS / 4 + r] = rstd; }
    }
    __syncthreads();

    // ---- Column partials (each thread: cols tid, tid+128) ----
    {
        float acc0 = 0.f, acc1 = 0.f;
#pragma unroll 4
        for (int r = 0; r < BR; r++) {
            const float muv = smf[OF_MU / 4 + r], rsv = smf[OF_RS / 4 + r];
            acc0 += (Os[r * OSS + tid]       - muv) * rsv;
            acc1 += (Os[r * OSS + tid + 128] - muv) * rsv;
        }
        float* gp = g_part + (size_t)(b * NTILE + qt) * C_;
        gp[tid]       = gamma[tid]       * acc0 + 64.f * beta[tid];
        gp[tid + 128] = gamma[tid + 128] * acc1 + 64.f * beta[tid + 128];
    }

    // ---- Last CTA of batch b reduces the 16 partials -> output ----
    __threadfence();
    __syncthreads();
    if (tid == 0) {
        int v = atomicAdd(&g_done[b], 1);
        lastflag = (v == NTILE - 1);
    }
    __syncthreads();
    if (lastflag) {
#pragma unroll
        for (int cc = 0; cc < 2; cc++) {
            const int c = tid + cc * 128;
            float s = 0.f;
#pragma unroll
            for (int q = 0; q < NTILE; q++)
                s += g_part[(size_t)(b * NTILE + q) * C_ + c];
            out[b * C_ + c] = s * (1.f / 1024.f);
        }
    }
}

// ---------------------------------------------------------------------------
extern "C" void kernel_launch(void* const* d_in, const int* in_sizes, int n_in,
                              void* d_out, int out_size)
{
    const float* x     = (const float*)d_in[0];
    const int*   km    = (const int*)  d_in[1];
    const float* gamma = (const float*)d_in[2];
    const float* beta  = (const float*)d_in[3];
    float*       out   = (float*)d_out;

    cudaFuncSetAttribute(attn_kernel,
                         cudaFuncAttributeMaxDynamicSharedMemorySize, SMEM_TOTAL);

    prep_kernel<<<dim3(B_, 16), 256>>>(x);
    scan_kernel<<<B_, 256>>>(km);
    attn_kernel<<<dim3(B_, NTILE), 128, SMEM_TOTAL>>>(gamma, beta, out);
}